// round 16
// baseline (speedup 1.0000x reference)
#include <cuda_runtime.h>
#include <cstdint>

#define H        768
#define HK       8                      // K floats per half-stage (32 B/row)
#define NHALF    (H / HK)               // 96 halves per pass
#define WROWS    128                    // rows per warp pass (4 per lane)
#define G        4
#define RSTRIDE  20                     // floats per row slot (16 + 4 pad)
#define ROWB     (RSTRIDE * 4)          // 80 B
#define CHUNK_FLOATS (WROWS * RSTRIDE)  // 2560 (one 16-k chunk = 2 halves)
#define CHUNK_BYTES  (CHUNK_FLOATS * 4) // 10240
#define WARPS    8                      // 256 threads, 1 CTA/SM
#define W4_FLOATS (H * 16)              // [H][4] float4 (48 KB)
#define W1_FLOATS (H)
#define WB_FLOATS 32
#define WX_FLOATS (W4_FLOATS + W1_FLOATS + WB_FLOATS)
#define SMEM_BYTES ((WX_FLOATS + WARPS * 2 * CHUNK_FLOATS) * 4)  // 216192 B

// 17 fused channels: a0,a1 | b0..b3 | c1_0,c1_1 | c2_0..2 | c3_0..3 | c4_0,c4_1

__device__ __forceinline__ void ffma2(float2& d, const float2 a, const float2 b)
{
    asm("fma.rn.f32x2 %0, %1, %2, %0;"
        : "+l"(reinterpret_cast<unsigned long long&>(d))
        : "l"(reinterpret_cast<const unsigned long long&>(a)),
          "l"(reinterpret_cast<const unsigned long long&>(b)));
}

__device__ __forceinline__ void cp16(uint32_t saddr, const void* gptr)
{
    asm volatile("cp.async.cg.shared.global [%0], [%1], 16;"
                 :: "r"(saddr), "l"(gptr) : "memory");
}
__device__ __forceinline__ void cp_commit()
{
    asm volatile("cp.async.commit_group;" ::: "memory");
}
template <int N>
__device__ __forceinline__ void cp_wait()
{
    asm volatile("cp.async.wait_group %0;" :: "n"(N) : "memory");
}

// ---------------------------------------------------------------------------
// Single-launch kernel. Per-CTA: pack weights+bias into smem from raw inputs,
// then each warp processes its 128-row tiles (static strided assignment).
// Staging: per warp 2 x 10 KB chunk buffers = ring of 4 disjoint 8-k half
// regions. Half h+3 is prefetched interleaved inside compute of half h
// (4 cp16 per jg-block) -> cp issue stream is smooth, not 16-wide bursts.
// ---------------------------------------------------------------------------
extern __shared__ float smem[];

__global__ void __launch_bounds__(WARPS * 32)
main_kernel(const float* __restrict__ x, float* __restrict__ out,
            const float* __restrict__ Wa,  const float* __restrict__ ba,
            const float* __restrict__ Wb,  const float* __restrict__ bb,
            const float* __restrict__ Wc1, const float* __restrict__ bc1,
            const float* __restrict__ Wc2, const float* __restrict__ bc2,
            const float* __restrict__ Wc3, const float* __restrict__ bc3,
            const float* __restrict__ Wc4, const float* __restrict__ bc4,
            int B, int ntiles)
{
    const int wid  = threadIdx.x >> 5;
    const int lane = threadIdx.x & 31;

    float4* sw4   = reinterpret_cast<float4*>(smem);    // [H][4]
    float*  sw1   = smem + W4_FLOATS;                   // [H]
    float*  sbias = sw1 + W1_FLOATS;                    // [17]
    float*  xbase = smem + WX_FLOATS;

    // ---- pack weights + bias into smem (per CTA, once) ----
    auto getw = [&](int ch, int k) -> float {
        if (ch < 2)  return Wa [ ch        * H + k];
        if (ch < 6)  return Wb [(ch - 2)  * H + k];
        if (ch < 8)  return Wc1[(ch - 6)  * H + k];
        if (ch < 11) return Wc2[(ch - 8)  * H + k];
        if (ch < 15) return Wc3[(ch - 11) * H + k];
        return Wc4[(ch - 15) * H + k];
    };
    for (int i = threadIdx.x; i < H * 4; i += WARPS * 32) {
        const int k = i >> 2, p = i & 3;
        sw4[i] = make_float4(getw(4 * p, k),     getw(4 * p + 1, k),
                             getw(4 * p + 2, k), getw(4 * p + 3, k));
    }
    for (int i = threadIdx.x; i < H; i += WARPS * 32)
        sw1[i] = getw(16, i);
    if (threadIdx.x < 17) {
        const int ch = threadIdx.x; float b;
        if      (ch < 2)  b = ba [ch];
        else if (ch < 6)  b = bb [ch - 2];
        else if (ch < 8)  b = bc1[ch - 6];
        else if (ch < 11) b = bc2[ch - 8];
        else if (ch < 15) b = bc3[ch - 11];
        else              b = bc4[ch - 15];
        sbias[ch] = b;
    }
    __syncthreads();

    float* xw = xbase + wid * (2 * CHUNK_FLOATS);
    const uint32_t sb = (uint32_t)__cvta_generic_to_shared(xw);

    // cp mapping per half: 2 lanes x 16 B cover one 32 B row segment;
    // one cp16 warp-inst covers 16 rows, 8 insts cover 128 rows.
    const int hrow  = lane >> 1;   // 0..15
    const int hpart = lane & 1;    // 0..1

    for (int tile = wid * gridDim.x + blockIdx.x; tile < ntiles;
         tile += WARPS * gridDim.x) {

        const int    row0 = tile * WROWS;
        const float* gx   = x + (size_t)row0 * H;

        // issue quarter q (4 cp16) of half h's loads
        auto load_q = [&](int h, int part) {
            const float* gsrc = gx + h * HK + (size_t)hrow * H + hpart * 4;
            const uint32_t d0 = sb + ((h >> 1) & 1) * CHUNK_BYTES
                                   + (h & 1) * 32 + hrow * ROWB + hpart * 16;
            #pragma unroll
            for (int q = 0; q < 4; ++q) {
                const int i = part * 4 + q;
                if (row0 + i * 16 + hrow < B)
                    cp16(d0 + i * 16 * ROWB, gsrc + (size_t)(i * 16) * H);
            }
        };

        float2 acc[G][8];
        float  a16[G];
        #pragma unroll
        for (int g = 0; g < G; ++g) {
            #pragma unroll
            for (int p = 0; p < 8; ++p) acc[g][p] = make_float2(0.f, 0.f);
            a16[g] = 0.f;
        }

        cp_wait<0>();                       // drain prior pass
        load_q(0, 0); load_q(0, 1); cp_commit();
        load_q(1, 0); load_q(1, 1); cp_commit();
        load_q(2, 0); load_q(2, 1); cp_commit();

        #pragma unroll 4
        for (int h = 0; h < NHALF; ++h) {
            cp_wait<2>();                   // this lane's half-h group retired
            __syncwarp();                   // all lanes' halves landed

            const float* xb = xw + ((h >> 1) & 1) * CHUNK_FLOATS;
            const int hp = h + 3;
            const bool pf = hp < NHALF;

            #pragma unroll
            for (int jj = 0; jj < 2; ++jj) {
                if (pf) load_q(hp, jj);     // interleaved prefetch (disjoint region)

                const int jg = (h & 1) * 2 + jj;
                float4 xv[G];
                #pragma unroll
                for (int g = 0; g < G; ++g)
                    xv[g] = *reinterpret_cast<const float4*>(
                        xb + (lane + 32 * g) * RSTRIDE + jg * 4);

                const int kb = (h >> 1) * 16 + jg * 4;
                #pragma unroll
                for (int j = 0; j < 4; ++j) {
                    const int k = kb + j;
                    const float4* wk = sw4 + k * 4;   // warp-uniform -> broadcast LDS
                    const float4 w0 = wk[0];
                    const float4 w1 = wk[1];
                    const float4 w2 = wk[2];
                    const float4 w3 = wk[3];
                    const float  wl = sw1[k];
                    #pragma unroll
                    for (int g = 0; g < G; ++g) {
                        const float xk = (j == 0) ? xv[g].x : (j == 1) ? xv[g].y
                                       : (j == 2) ? xv[g].z : xv[g].w;
                        const float2 xd = make_float2(xk, xk);
                        ffma2(acc[g][0], xd, make_float2(w0.x, w0.y));
                        ffma2(acc[g][1], xd, make_float2(w0.z, w0.w));
                        ffma2(acc[g][2], xd, make_float2(w1.x, w1.y));
                        ffma2(acc[g][3], xd, make_float2(w1.z, w1.w));
                        ffma2(acc[g][4], xd, make_float2(w2.x, w2.y));
                        ffma2(acc[g][5], xd, make_float2(w2.z, w2.w));
                        ffma2(acc[g][6], xd, make_float2(w3.x, w3.y));
                        ffma2(acc[g][7], xd, make_float2(w3.z, w3.w));
                        a16[g] = fmaf(xk, wl, a16[g]);
                    }
                }
            }
            __syncwarp();
            cp_commit();                    // one group per half (may be empty)
        }

        // --- epilogue: bias, routing, masked scattered stores (4 rows/lane) ---
        #pragma unroll
        for (int g = 0; g < G; ++g) {
            const int r = row0 + lane + 32 * g;
            if (r >= B) continue;

            float v[17];
            #pragma unroll
            for (int p = 0; p < 8; ++p) {
                v[2 * p]     = acc[g][p].x + sbias[2 * p];
                v[2 * p + 1] = acc[g][p].y + sbias[2 * p + 1];
            }
            v[16] = a16[g] + sbias[16];

            const bool active = v[1] > v[0];               // argmax(out_a) != 0

            ((float2*)out)[r] = make_float2(v[0], v[1]);   // out_a

            int pb = 0; float best = v[2];
            if (v[3] > best) { pb = 1; best = v[3]; }
            if (v[4] > best) { pb = 2; best = v[4]; }
            if (v[5] > best) { pb = 3; best = v[5]; }

            float* ob = out + 2 * (size_t)B + 5 * (size_t)r;   // out_b
            ob[0] = 0.0f;
            #pragma unroll
            for (int j = 0; j < 4; ++j) ob[j + 1] = active ? v[2 + j] : 0.0f;

            float* oc = out + 7 * (size_t)B + 11 * (size_t)r;  // out_c
            #pragma unroll
            for (int j = 0; j < 11; ++j) {
                const int hd = (j < 2) ? 0 : (j < 5) ? 1 : (j < 9) ? 2 : 3;
                oc[j] = (active && hd == pb) ? v[6 + j] : 0.0f;
            }
        }
    }
}

// ---------------------------------------------------------------------------
extern "C" void kernel_launch(void* const* d_in, const int* in_sizes, int n_in,
                              void* d_out, int out_size)
{
    const float* x = (const float*)d_in[0];
    const int B = in_sizes[0] / H;
    const int ntiles = (B + WROWS - 1) / WROWS;   // 1024 for B=131072
    const int grid   = 148;                        // 1 CTA/SM; static strided tiles

    cudaFuncSetAttribute(main_kernel,
                         cudaFuncAttributeMaxDynamicSharedMemorySize, SMEM_BYTES);
    main_kernel<<<grid, WARPS * 32, SMEM_BYTES>>>(
        x, (float*)d_out,
        (const float*)d_in[1],  (const float*)d_in[2],
        (const float*)d_in[3],  (const float*)d_in[4],
        (const float*)d_in[5],  (const float*)d_in[6],
        (const float*)d_in[7],  (const float*)d_in[8],
        (const float*)d_in[9],  (const float*)d_in[10],
        (const float*)d_in[11], (const float*)d_in[12],
        B, ntiles);
}